// round 17
// baseline (speedup 1.0000x reference)
#include <cuda_runtime.h>
#include <cstddef>

#define BSZ   256
#define NN    2048
#define KK    64
#define KP1   65
#define NT    256
#define RPT   8
#define NWARP 8
#define DD    14          // Taylor degree
#define QRS   16          // Qr row stride
#define QCS   66          // Qc row stride
#define TSTR  68          // T-partial row stride
#define MAXIT 200
#define EPS_F 0.1f
#define CONV_TOL 2e-4f
#define MU_F  (1.f/2048.f)

typedef unsigned long long u64;

__device__ unsigned g_maxEnc = 0u;
__device__ unsigned g_minEnc = 0xffffffffu;
__device__ int      g_anyMask = 0;
__device__ int      g_t1 = 0;
__device__ int      g_t2 = 0;
__device__ int      g_phase = 0;
__device__ float    g_alpha;
__device__ float    g_filled;
__device__ float    g_sbar;
__device__ float    g_normPart[BSZ];

__device__ __forceinline__ u64 pack2(float lo, float hi){
  u64 r; asm("mov.b64 %0, {%1,%2};" : "=l"(r) : "f"(lo), "f"(hi)); return r;
}
__device__ __forceinline__ void unpack2(u64 v, float& lo, float& hi){
  asm("mov.b64 {%0,%1}, %2;" : "=f"(lo), "=f"(hi) : "l"(v));
}
__device__ __forceinline__ u64 fma2(u64 a, u64 b, u64 c){
  u64 d; asm("fma.rn.f32x2 %0, %1, %2, %3;" : "=l"(d) : "l"(a), "l"(b), "l"(c)); return d;
}
__device__ __forceinline__ u64 mul2(u64 a, u64 b){
  u64 d; asm("mul.rn.f32x2 %0, %1, %2;" : "=l"(d) : "l"(a), "l"(b)); return d;
}
__device__ __forceinline__ u64 add2(u64 a, u64 b){
  u64 d; asm("add.rn.f32x2 %0, %1, %2;" : "=l"(d) : "l"(a), "l"(b)); return d;
}
__device__ __forceinline__ float tanhA(float x){
  float r; asm("tanh.approx.f32 %0, %1;" : "=f"(r) : "f"(x)); return r;
}
__device__ __forceinline__ unsigned encF(float f){
  unsigned u = __float_as_uint(f);
  return (u & 0x80000000u) ? ~u : (u | 0x80000000u);
}
__device__ __forceinline__ float decF(unsigned e){
  unsigned u = (e & 0x80000000u) ? (e & 0x7fffffffu) : ~e;
  return __uint_as_float(u);
}

__global__ void __launch_bounds__(NT, 2) k_all(
    const float* __restrict__ scores,
    const float* __restrict__ W,
    float* __restrict__ out)
{
  __shared__ __align__(16) float sh_s[NN];
  __shared__ __align__(16) float sh_y[NN];
  __shared__ __align__(16) float sh_w[NN];
  __shared__ __align__(16) float sh_red[NN+64];
  __shared__ __align__(16) float sh_Qc[DD*QCS];
  __shared__ __align__(16) float sh_Qr[KP1*QRS];
  __shared__ float sh_chi[KP1];
  __shared__ float sh_C[DD];
  __shared__ float sh_T[DD];
  __shared__ float sh_tk[KK];
  __shared__ float sh_invZn[KK];
  __shared__ float sh_wred[NWARP];
  __shared__ float sh_par[3];
  __shared__ float sh_scalar[1];
  __shared__ unsigned sMx[NWARP], sMn[NWARP], sAn[NWARP];
  __shared__ int   sh_conv[2];
  __shared__ int   sh_last;

  const int tid  = threadIdx.x;
  const int wid  = tid >> 5;
  const int lane = tid & 31;
  const int b    = blockIdx.x;
  const float ninf = __int_as_float(0xff800000);
  const float* sc = scores + (size_t)b*NN;

  // ===== phase A: load + local min/max/any + global params via ticket/spin =====
  unsigned mx=0u, mn=0xffffffffu, any=0u;
  #pragma unroll
  for (int j=0;j<RPT;j++){
    int n = tid + j*NT;
    float x = sc[n];
    sh_s[n] = x;
    bool neg = (x==ninf);
    any |= (neg?1u:0u);
    unsigned e = encF(x);
    mx = max(mx,e);
    mn = min(mn, neg?0xffffffffu:e);
  }
  mx=__reduce_max_sync(0xffffffffu,mx);
  mn=__reduce_min_sync(0xffffffffu,mn);
  any=__reduce_or_sync(0xffffffffu,any);
  if (lane==0){ sMx[wid]=mx; sMn[wid]=mn; sAn[wid]=any; }
  __syncthreads();
  if (tid==0){
    #pragma unroll
    for (int q=1;q<NWARP;q++){ mx=max(mx,sMx[q]); mn=min(mn,sMn[q]); any|=sAn[q]; }
    atomicMax(&g_maxEnc,mx); atomicMin(&g_minEnc,mn);
    if (any) atomicOr(&g_anyMask,1);
    __threadfence();
    if (atomicAdd(&g_t1,1) == BSZ-1){
      unsigned MX=*(volatile unsigned*)&g_maxEnc;
      unsigned MN=*(volatile unsigned*)&g_minEnc;
      int AN=*(volatile int*)&g_anyMask;
      float maxS=decF(MX), minS=decF(MN);
      float filled = minS-(maxS-minS);
      float minF = AN ? fminf(filled,minS) : minS;
      float maxF = fmaxf(maxS,minF);
      float c1=minF*minF, c2=maxF*maxF;
      float c3=(minF-64.f)*(minF-64.f), c4=(maxF-64.f)*(maxF-64.f);
      float cmax=fmaxf(fmaxf(c1,c2),fmaxf(c3,c4));
      *(volatile float*)&g_alpha  = 1.f/(EPS_F*cmax);
      *(volatile float*)&g_filled = filled;
      *(volatile float*)&g_sbar   = 0.5f*(minF+maxF);
      __threadfence();
      *(volatile int*)&g_phase = 1;
    }
    while (*(volatile int*)&g_phase == 0) __nanosleep(64);
    __threadfence();
    sh_par[0]=*(volatile float*)&g_alpha;
    sh_par[1]=*(volatile float*)&g_filled;
    sh_par[2]=*(volatile float*)&g_sbar;
  }
  __syncthreads();
  const float alpha  = sh_par[0];
  const float filled = sh_par[1];
  const float sbar   = sh_par[2];

  #pragma unroll
  for (int j=0;j<RPT;j++){
    int n = tid + j*NT;
    float x = sh_s[n];
    if (x == ninf) sh_s[n] = filled;
  }
  // precompute Q matrices + chi init
  float h0=0.f, h1=0.f, oldc=0.f;
  if (tid < KP1){
    float a   = (float)tid;
    float lam = 2.f*alpha*a;
    float q = 1.f;
    sh_Qr[tid*QRS+0] = 1.f;
    sh_Qc[0*QCS+tid] = 1.f;
    #pragma unroll
    for (int d=1; d<DD; d++){
      q = q * lam / (float)d;
      sh_Qr[tid*QRS+d] = q;
      sh_Qc[d*QCS+tid] = q;
    }
    float da = a - sbar;
    float c = __expf(-alpha*da*da) * (1.f/(float)KP1);
    sh_chi[tid] = c;
    h0 = c; h1 = c; oldc = c;
  }
  if (tid == 0){ sh_conv[0]=0; sh_conv[1]=0; }
  __syncthreads();

  // ds = s - sbar, packed
  u64 ds2[4];
  #pragma unroll
  for (int q=0;q<4;q++){
    float da = sh_s[tid + (2*q  )*NT] - sbar;
    float db = sh_s[tid + (2*q+1)*NT] - sbar;
    ds2[q] = pack2(da, db);
  }
  u64 y2[4];

  // ===== Sinkhorn loop (Taylor-compressed) =====
  #pragma unroll 1
  for (int it=0; it<MAXIT; ++it){
    if (tid < DD){                       // step1: C_d = sum_a chi_a * Q[d][a]
      const float* qc = &sh_Qc[tid*QCS];
      float c0=0.f,c1=0.f,c2=0.f,c3=0.f;
      #pragma unroll
      for (int a=0; a<64; a+=4){
        c0 += sh_chi[a  ]*qc[a  ];
        c1 += sh_chi[a+1]*qc[a+1];
        c2 += sh_chi[a+2]*qc[a+2];
        c3 += sh_chi[a+3]*qc[a+3];
      }
      sh_C[tid] = ((c0+c1)+(c2+c3)) + sh_chi[64]*qc[64];
    }
    __syncthreads();
    {                                    // step2: acc = poly(C, ds), y = MU/acc
      float cT = sh_C[DD-1];
      u64 a0=pack2(cT,cT), a1=a0, a2=a0, a3=a0;
      #pragma unroll
      for (int d=DD-2; d>=0; --d){
        float c = sh_C[d];
        u64 f = pack2(c,c);
        a0=fma2(a0,ds2[0],f); a1=fma2(a1,ds2[1],f); a2=fma2(a2,ds2[2],f); a3=fma2(a3,ds2[3],f);
      }
      float lo,hi;
      unpack2(a0,lo,hi); y2[0]=pack2(__fdividef(MU_F,lo), __fdividef(MU_F,hi));
      unpack2(a1,lo,hi); y2[1]=pack2(__fdividef(MU_F,lo), __fdividef(MU_F,hi));
      unpack2(a2,lo,hi); y2[2]=pack2(__fdividef(MU_F,lo), __fdividef(MU_F,hi));
      unpack2(a3,lo,hi); y2[3]=pack2(__fdividef(MU_F,lo), __fdividef(MU_F,hi));
    }
    {                                    // step3: T-partials T_d = sum_n y*ds^d
      u64 t0=y2[0], t1=y2[1], t2=y2[2], t3=y2[3];
      #pragma unroll
      for (int d=0; d<DD; d++){
        u64 p = add2(add2(t0,t1), add2(t2,t3));
        float lo,hi; unpack2(p,lo,hi);
        float mv = lo + hi;
        mv += __shfl_xor_sync(0xffffffffu, mv, 16);
        mv += __shfl_xor_sync(0xffffffffu, mv, 8);
        if (lane < 8) sh_red[d*TSTR + wid*8 + lane] = mv;
        if (d < DD-1){
          t0=mul2(t0,ds2[0]); t1=mul2(t1,ds2[1]); t2=mul2(t2,ds2[2]); t3=mul2(t3,ds2[3]);
        }
      }
    }
    __syncthreads();
    if (tid < 96){                       // owner region (warps 0-2)
      if (tid < DD){                     // step4: T_d final (64 adds)
        const float4* r4 = (const float4*)&sh_red[tid*TSTR];
        float s0=0.f,s1=0.f,s2=0.f,s3=0.f;
        #pragma unroll
        for (int p=0;p<16;p+=4){
          float4 v0=r4[p], v1=r4[p+1], v2=r4[p+2], v3=r4[p+3];
          s0 += (v0.x+v0.y)+(v0.z+v0.w);
          s1 += (v1.x+v1.y)+(v1.z+v1.w);
          s2 += (v2.x+v2.y)+(v2.z+v2.w);
          s3 += (v3.x+v3.y)+(v3.z+v3.w);
        }
        sh_T[tid] = (s0+s1)+(s2+s3);
      }
      asm volatile("bar.sync 1, 96;" ::: "memory");
      if (tid < KP1){                    // step5: S_a, chi update, Steffensen
        const float* qr = &sh_Qr[tid*QRS];
        float S = 0.f;
        #pragma unroll
        for (int d=0; d<DD; d++) S += qr[d]*sh_T[d];
        float nuv = (tid==0) ? ((float)(NN-KK)/(float)NN) : MU_F;
        float newc = __fdividef(nuv, S);
        if (fabsf(newc - oldc) > CONV_TOL*fabsf(oldc)) sh_conv[it&1] = 1;
        float store = newc;
        if ((it & 1) == 0){
          h1 = newc;
        } else {
          float d1 = h1 - h0, d2 = newc - h1;
          float den = d2 - d1;
          if (fabsf(den) > 1e-30f){
            float ext = newc - (d2*d2)/den;
            if (ext > 0.f && isfinite(ext)) store = ext;
          }
          h0 = store;
        }
        sh_chi[tid] = store;
        oldc = store;
        if (tid == 0) sh_conv[(it+1)&1] = 0;
      }
    }
    __syncthreads();
    if (sh_conv[it&1] == 0) break;
  }

  // stage y and w to SMEM for the coalesced final pass (sort barrier orders reads)
  #pragma unroll
  for (int q=0;q<4;q++){
    float lo,hi;
    unpack2(y2[q],lo,hi);
    sh_y[tid+(2*q)*NT]=lo; sh_y[tid+(2*q+1)*NT]=hi;
    unpack2(ds2[q],lo,hi);
    sh_w[tid+(2*q)*NT]=__expf(2.f*alpha*lo);
    sh_w[tid+(2*q+1)*NT]=__expf(2.f*alpha*hi);
  }

  // ===== hybrid bitonic sort: 8 consecutive elems per thread =====
  float sv[8];
  const int base8 = tid*8;
  {
    float4 p0 = *(const float4*)&sh_s[base8];
    float4 p1 = *(const float4*)&sh_s[base8+4];
    sv[0]=p0.x; sv[1]=p0.y; sv[2]=p0.z; sv[3]=p0.w;
    sv[4]=p1.x; sv[5]=p1.y; sv[6]=p1.z; sv[7]=p1.w;
  }
  for (int kk2=2; kk2<=NN; kk2<<=1){
    for (int jj=kk2>>1; jj>=256; jj>>=1){
      *(float4*)&sh_red[base8]   = make_float4(sv[0],sv[1],sv[2],sv[3]);
      *(float4*)&sh_red[base8+4] = make_float4(sv[4],sv[5],sv[6],sv[7]);
      __syncthreads();
      int delta = jj>>3;
      int pc = tid ^ delta;
      bool tmin = (((base8 & kk2)==0) == ((tid & delta)==0));
      float4 q0 = *(const float4*)&sh_red[pc*8];
      float4 q1 = *(const float4*)&sh_red[pc*8+4];
      float o[8] = {q0.x,q0.y,q0.z,q0.w,q1.x,q1.y,q1.z,q1.w};
      #pragma unroll
      for (int m=0;m<8;m++) sv[m] = tmin ? fminf(sv[m],o[m]) : fmaxf(sv[m],o[m]);
      __syncthreads();
    }
    {
      int jj0 = (kk2>>1) > 128 ? 128 : (kk2>>1);
      for (int jj=jj0; jj>=8; jj>>=1){
        int delta = jj>>3;
        bool tmin = (((base8 & kk2)==0) == ((tid & delta)==0));
        #pragma unroll
        for (int m=0;m<8;m++){
          float o = __shfl_xor_sync(0xffffffffu, sv[m], delta);
          sv[m] = tmin ? fminf(sv[m],o) : fmaxf(sv[m],o);
        }
      }
    }
    {
      int jj0 = (kk2>>1) > 4 ? 4 : (kk2>>1);
      for (int jj=jj0; jj>=1; jj>>=1){
        #pragma unroll
        for (int m=0;m<8;m++){
          if ((m & jj)==0){
            int m2 = m | jj;
            bool asc = (((base8+m) & kk2)==0);
            float a=sv[m], bb=sv[m2];
            if ((a>bb)==asc){ sv[m]=bb; sv[m2]=a; }
          }
        }
      }
    }
  }

  // ===== tau + top-K =====
  {
    float4 w0 = *(const float4*)&W[base8];
    float4 w1 = *(const float4*)&W[base8+4];
    float part = sv[0]*w0.x + sv[1]*w0.y + sv[2]*w0.z + sv[3]*w0.w
               + sv[4]*w1.x + sv[5]*w1.y + sv[6]*w1.z + sv[7]*w1.w;
    #pragma unroll
    for (int o=16;o>0;o>>=1) part += __shfl_xor_sync(0xffffffffu, part, o);
    if (lane==0) sh_wred[wid] = part;
    if (tid >= NT-8){
      #pragma unroll
      for (int m=0;m<8;m++) sh_tk[NN-1-base8-m] = sv[m];
    }
    __syncthreads();
    if (tid==0){
      float tau=0.f;
      #pragma unroll
      for (int q=0;q<NWARP;q++) tau += sh_wred[q];
      sh_scalar[0] = 0.5f/tau;
    }
    __syncthreads();
  }
  const float hTau = sh_scalar[0];

  // ===== Gamma0 column sums Z_k =====
  #pragma unroll 1
  for (int c=0;c<4;c++){
    float z[16];
    #pragma unroll
    for (int q=0;q<16;q++) z[q]=0.f;
    #pragma unroll
    for (int j=0;j<RPT;j++){
      float s = sh_s[tid+j*NT];
      #pragma unroll
      for (int q=0;q<16;q++){
        float d = fabsf(sh_tk[c*16+q]-s);
        z[q] += fmaf(-0.5f, tanhA(d*hTau), 0.5f);
      }
    }
    #pragma unroll
    for (int q=0;q<16;q++){
      float mv = z[q];
      #pragma unroll
      for (int o=16;o>0;o>>=1) mv += __shfl_xor_sync(0xffffffffu, mv, o);
      if (lane==0) sh_red[q*NWARP + wid] = mv;
    }
    __syncthreads();
    if (tid < 16){
      float Z=0.f;
      #pragma unroll
      for (int q=0;q<NWARP;q++) Z += sh_red[tid*NWARP+q];
      sh_invZn[c*16+tid] = __fdividef(1.f, Z*(float)NN);
    }
    __syncthreads();
  }

  // ===== final pass: warp-coalesced, 4 rows/pass =====
  // lane = rg*8 + jw; lane covers row (base+pass*4+rg), k in [4jw,4jw+4) u [32+4jw,36+4jw)
  {
    const int rg = lane >> 3;
    const int jw = lane & 7;
    const float twoA = 2.f*alpha;
    const int rbase = wid*256;
    const float chi0 = sh_chi[0];
    float nrm = 0.f;
    #pragma unroll 1
    for (int pass=0; pass<64; ++pass){
      int r = rbase + pass*4 + rg;
      float s = sh_s[r];
      float y = sh_y[r];
      float w = sh_w[r];
      float ds = s - sbar;
      float t1 = y * __expf(twoA*ds*(float)(61-4*jw));   // y*w^(a_min1)
      float t2 = t1 * __expf(-32.f*twoA*ds);             // a2 = a1 - 32
      float* orow = out + ((size_t)b*NN + r)*KK;
      float rs = 0.f;
      float o1[4], o2[4];
      #pragma unroll
      for (int m=0;m<4;m++){
        int a1 = 61-4*jw+m;       // k1 = 64-a1 = 3+4jw-m
        int k1 = 3+4*jw-m;
        float gam1 = t1*sh_chi[a1];
        float d1 = fabsf(sh_tk[k1]-s);
        float sg1 = fmaf(-0.5f, tanhA(d1*hTau), 0.5f);
        float g01 = sg1*sh_invZn[k1];
        rs += g01;
        float df1 = gam1-g01; nrm = fmaf(df1,df1,nrm);
        o1[3-m] = gam1*2048.f;
        int a2 = a1-32, k2 = k1+32;
        float gam2 = t2*sh_chi[a2];
        float d2v = fabsf(sh_tk[k2]-s);
        float sg2 = fmaf(-0.5f, tanhA(d2v*hTau), 0.5f);
        float g02 = sg2*sh_invZn[k2];
        rs += g02;
        float df2 = gam2-g02; nrm = fmaf(df2,df2,nrm);
        o2[3-m] = gam2*2048.f;
        t1 *= w; t2 *= w;
      }
      *(float4*)(orow + 4*jw)      = make_float4(o1[0],o1[1],o1[2],o1[3]);
      *(float4*)(orow + 32 + 4*jw) = make_float4(o2[0],o2[1],o2[2],o2[3]);
      rs += __shfl_xor_sync(0xffffffffu, rs, 1);
      rs += __shfl_xor_sync(0xffffffffu, rs, 2);
      rs += __shfl_xor_sync(0xffffffffu, rs, 4);
      if (jw==0){
        float gam64 = y*chi0;
        float last = MU_F - rs;
        last = fminf(fmaxf(last, 1e-20f), 1.f-1e-20f);
        float dl = gam64 - last;
        nrm = fmaf(dl, dl, nrm);
      }
    }
    #pragma unroll
    for (int o=16;o>0;o>>=1) nrm += __shfl_xor_sync(0xffffffffu, nrm, o);
    if (lane==0) sh_wred[wid] = nrm;
  }
  __syncthreads();
  if (tid==0){
    float sA=0.f;
    #pragma unroll
    for (int q=0;q<NWARP;q++) sA += sh_wred[q];
    g_normPart[b] = sA;
  }

  // ===== final norm via last-CTA ticket (self-resetting globals) =====
  if (tid==0){
    __threadfence();
    sh_last = (atomicAdd(&g_t2,1) == BSZ-1) ? 1 : 0;
  }
  __syncthreads();
  if (sh_last){
    __threadfence();
    float v = *(volatile float*)&g_normPart[tid];
    #pragma unroll
    for (int o=16;o>0;o>>=1) v += __shfl_xor_sync(0xffffffffu, v, o);
    if (lane==0) sh_wred[wid] = v;
    __syncthreads();
    if (tid==0){
      float sT=0.f;
      #pragma unroll
      for (int q=0;q<NWARP;q++) sT += sh_wred[q];
      out[(size_t)BSZ*NN*KK] = sqrtf(sT);
      g_t1=0; g_t2=0;
      g_maxEnc=0u; g_minEnc=0xffffffffu; g_anyMask=0;
      __threadfence();
      *(volatile int*)&g_phase = 0;
    }
  }
}

extern "C" void kernel_launch(void* const* d_in, const int* in_sizes, int n_in,
                              void* d_out, int out_size)
{
  const float* scores = (const float*)d_in[0];
  const float* W      = (const float*)d_in[1];
  if (n_in >= 2 && in_sizes[0] == NN && in_sizes[1] == BSZ*NN){
    const float* tmp = scores; scores = W; W = tmp;
  }
  float* out = (float*)d_out;
  (void)out_size;

  k_all<<<BSZ, NT>>>(scores, W, out);
}